// round 2
// baseline (speedup 1.0000x reference)
#include <cuda_runtime.h>
#include <math.h>

#define BB 4096
#define LAT 256
#define HH 512
#define AA 64
#define LL 128

// ---- scratch (static device globals; no runtime allocation) ----
__device__ float g_Hall[(size_t)LL * BB * HH];        // h after step t at slot t (slot 0 = h0)  ~1.07 GB
__device__ float g_P1[(size_t)(LL - 1) * BB * HH];    // decoder stage-1 activations            ~1.06 GB
__device__ float g_P2[(size_t)(LL - 1) * BB * AA];    // decoder stage-2 activations            ~133 MB
__device__ float g_t1[(size_t)BB * HH];
__device__ float g_t2[(size_t)BB * HH];
__device__ float g_xbos[(size_t)BB * AA];

// ============================================================
// Fill kernels: BOS pseudo one-hot (-16 everywhere, +16 at idx 0)
// ============================================================
__global__ void fill_bos_out(float* __restrict__ out) {
    int idx = blockIdx.x * blockDim.x + threadIdx.x;   // [0, BB*AA)
    int b = idx >> 6;
    int a = idx & 63;
    out[(size_t)b * (LL * AA) + a] = (a == 0) ? 16.0f : -16.0f;
}

__global__ void fill_xbos(float* __restrict__ xb) {
    int idx = blockIdx.x * blockDim.x + threadIdx.x;
    int a = idx & 63;
    xb[idx] = (a == 0) ? 16.0f : -16.0f;
}

// ============================================================
// Generic GEMM: C = act(A[M,K] @ W[N,K]^T + bias)
// 64x64 tile, 256 threads, 4x4 per thread, BK=16.
// ACT: 0 = none, 1 = tanh. SCATTER: remap row m=(t-1)*B+b -> out[b, t, n].
// Requires M%64==0, N%64==0, K%16==0.
// ============================================================
template <int ACT, bool SCATTER>
__global__ void __launch_bounds__(256)
gemm_bias_act(const float* __restrict__ Ap, long lda,
              const float* __restrict__ Wp, int K,
              const float* __restrict__ bias,
              float* __restrict__ Cp, long ldc)
{
    __shared__ float As[16][64];
    __shared__ float Ws[16][64];

    const int tid = threadIdx.x;
    const int r = tid >> 2;        // 0..63 (load row)
    const int c = tid & 3;         // 0..3  (load k-chunk)
    const int tx = tid & 15;       // 0..15 (output col group)
    const int ty = tid >> 4;       // 0..15 (output row group)

    const long m0 = (long)blockIdx.x * 64;
    const int  n0 = blockIdx.y * 64;

    float acc[4][4];
#pragma unroll
    for (int i = 0; i < 4; ++i)
#pragma unroll
        for (int j = 0; j < 4; ++j) acc[i][j] = 0.0f;

    for (int k0 = 0; k0 < K; k0 += 16) {
        float4 av = *(const float4*)(Ap + (m0 + r) * lda + k0 + 4 * c);
        float4 wv = *(const float4*)(Wp + (long)(n0 + r) * K + k0 + 4 * c);
        __syncthreads();
        As[4 * c + 0][r] = av.x; As[4 * c + 1][r] = av.y;
        As[4 * c + 2][r] = av.z; As[4 * c + 3][r] = av.w;
        Ws[4 * c + 0][r] = wv.x; Ws[4 * c + 1][r] = wv.y;
        Ws[4 * c + 2][r] = wv.z; Ws[4 * c + 3][r] = wv.w;
        __syncthreads();
#pragma unroll
        for (int k = 0; k < 16; ++k) {
            float4 a4 = *(const float4*)(&As[k][ty * 4]);
            float4 w4 = *(const float4*)(&Ws[k][tx * 4]);
            float a[4] = {a4.x, a4.y, a4.z, a4.w};
            float w[4] = {w4.x, w4.y, w4.z, w4.w};
#pragma unroll
            for (int i = 0; i < 4; ++i)
#pragma unroll
                for (int j = 0; j < 4; ++j)
                    acc[i][j] = fmaf(a[i], w[j], acc[i][j]);
        }
    }

    const long mb = m0 + ty * 4;
    const int  nb = n0 + tx * 4;
#pragma unroll
    for (int i = 0; i < 4; ++i) {
#pragma unroll
        for (int j = 0; j < 4; ++j) {
            float v = acc[i][j] + bias[nb + j];
            if (ACT == 1) v = tanhf(v);
            if (SCATTER) {
                long m = mb + i;
                long t = (m >> 12) + 1;      // m / 4096 + 1
                long b = m & 4095;
                Cp[b * (LL * AA) + t * AA + (nb + j)] = v;
            } else {
                Cp[(mb + i) * ldc + (nb + j)] = v;
            }
        }
    }
}

// ============================================================
// Fused GRU step: h_new = GRU(h_prev, x)
// gates = x @ W_ih^T + h @ W_hh^T (+biases); torch gate order r,z,n.
// n-gate keeps x-part and h-part separate (r multiplies the h-part).
// Tile: 64 (batch) x 64 (hidden cols), 256 threads, 4x4x{r,z,in,hn}.
// ============================================================
__global__ void __launch_bounds__(256)
gru_step(const float* __restrict__ x, long ldx,
         const float* __restrict__ hprev,
         const float* __restrict__ Wih,
         const float* __restrict__ Whh,
         const float* __restrict__ bih,
         const float* __restrict__ bhh,
         float* __restrict__ hnew)
{
    __shared__ float As[16][64];
    __shared__ float Ws3[3][16][64];

    const int tid = threadIdx.x;
    const int r = tid >> 2;
    const int c = tid & 3;
    const int tx = tid & 15;
    const int ty = tid >> 4;

    const long m0 = (long)blockIdx.x * 64;   // batch offset
    const int  n0 = blockIdx.y * 64;         // hidden-col offset

    float accr[4][4], accz[4][4], acci[4][4], acch[4][4];
#pragma unroll
    for (int i = 0; i < 4; ++i)
#pragma unroll
        for (int j = 0; j < 4; ++j) {
            accr[i][j] = 0.f; accz[i][j] = 0.f;
            acci[i][j] = 0.f; acch[i][j] = 0.f;
        }

    // ---- phase 1: x @ W_ih^T  (K = AA = 64), fills r,z,in ----
    for (int k0 = 0; k0 < AA; k0 += 16) {
        float4 av = *(const float4*)(x + (m0 + r) * ldx + k0 + 4 * c);
        float4 w0 = *(const float4*)(Wih + (long)(0 * HH + n0 + r) * AA + k0 + 4 * c);
        float4 w1 = *(const float4*)(Wih + (long)(1 * HH + n0 + r) * AA + k0 + 4 * c);
        float4 w2 = *(const float4*)(Wih + (long)(2 * HH + n0 + r) * AA + k0 + 4 * c);
        __syncthreads();
        As[4 * c + 0][r] = av.x; As[4 * c + 1][r] = av.y;
        As[4 * c + 2][r] = av.z; As[4 * c + 3][r] = av.w;
        Ws3[0][4 * c + 0][r] = w0.x; Ws3[0][4 * c + 1][r] = w0.y;
        Ws3[0][4 * c + 2][r] = w0.z; Ws3[0][4 * c + 3][r] = w0.w;
        Ws3[1][4 * c + 0][r] = w1.x; Ws3[1][4 * c + 1][r] = w1.y;
        Ws3[1][4 * c + 2][r] = w1.z; Ws3[1][4 * c + 3][r] = w1.w;
        Ws3[2][4 * c + 0][r] = w2.x; Ws3[2][4 * c + 1][r] = w2.y;
        Ws3[2][4 * c + 2][r] = w2.z; Ws3[2][4 * c + 3][r] = w2.w;
        __syncthreads();
#pragma unroll
        for (int k = 0; k < 16; ++k) {
            float4 a4 = *(const float4*)(&As[k][ty * 4]);
            float4 r4 = *(const float4*)(&Ws3[0][k][tx * 4]);
            float4 z4 = *(const float4*)(&Ws3[1][k][tx * 4]);
            float4 n4 = *(const float4*)(&Ws3[2][k][tx * 4]);
            float a[4] = {a4.x, a4.y, a4.z, a4.w};
            float wr[4] = {r4.x, r4.y, r4.z, r4.w};
            float wz[4] = {z4.x, z4.y, z4.z, z4.w};
            float wn[4] = {n4.x, n4.y, n4.z, n4.w};
#pragma unroll
            for (int i = 0; i < 4; ++i)
#pragma unroll
                for (int j = 0; j < 4; ++j) {
                    accr[i][j] = fmaf(a[i], wr[j], accr[i][j]);
                    accz[i][j] = fmaf(a[i], wz[j], accz[i][j]);
                    acci[i][j] = fmaf(a[i], wn[j], acci[i][j]);
                }
        }
    }

    // ---- phase 2: h @ W_hh^T  (K = HH = 512), fills r,z,hn ----
    for (int k0 = 0; k0 < HH; k0 += 16) {
        float4 av = *(const float4*)(hprev + (m0 + r) * HH + k0 + 4 * c);
        float4 w0 = *(const float4*)(Whh + (long)(0 * HH + n0 + r) * HH + k0 + 4 * c);
        float4 w1 = *(const float4*)(Whh + (long)(1 * HH + n0 + r) * HH + k0 + 4 * c);
        float4 w2 = *(const float4*)(Whh + (long)(2 * HH + n0 + r) * HH + k0 + 4 * c);
        __syncthreads();
        As[4 * c + 0][r] = av.x; As[4 * c + 1][r] = av.y;
        As[4 * c + 2][r] = av.z; As[4 * c + 3][r] = av.w;
        Ws3[0][4 * c + 0][r] = w0.x; Ws3[0][4 * c + 1][r] = w0.y;
        Ws3[0][4 * c + 2][r] = w0.z; Ws3[0][4 * c + 3][r] = w0.w;
        Ws3[1][4 * c + 0][r] = w1.x; Ws3[1][4 * c + 1][r] = w1.y;
        Ws3[1][4 * c + 2][r] = w1.z; Ws3[1][4 * c + 3][r] = w1.w;
        Ws3[2][4 * c + 0][r] = w2.x; Ws3[2][4 * c + 1][r] = w2.y;
        Ws3[2][4 * c + 2][r] = w2.z; Ws3[2][4 * c + 3][r] = w2.w;
        __syncthreads();
#pragma unroll
        for (int k = 0; k < 16; ++k) {
            float4 a4 = *(const float4*)(&As[k][ty * 4]);
            float4 r4 = *(const float4*)(&Ws3[0][k][tx * 4]);
            float4 z4 = *(const float4*)(&Ws3[1][k][tx * 4]);
            float4 n4 = *(const float4*)(&Ws3[2][k][tx * 4]);
            float a[4] = {a4.x, a4.y, a4.z, a4.w};
            float wr[4] = {r4.x, r4.y, r4.z, r4.w};
            float wz[4] = {z4.x, z4.y, z4.z, z4.w};
            float wn[4] = {n4.x, n4.y, n4.z, n4.w};
#pragma unroll
            for (int i = 0; i < 4; ++i)
#pragma unroll
                for (int j = 0; j < 4; ++j) {
                    accr[i][j] = fmaf(a[i], wr[j], accr[i][j]);
                    accz[i][j] = fmaf(a[i], wz[j], accz[i][j]);
                    acch[i][j] = fmaf(a[i], wn[j], acch[i][j]);
                }
        }
    }

    // ---- gate fusion epilogue ----
#pragma unroll
    for (int i = 0; i < 4; ++i) {
        const long m = m0 + ty * 4 + i;
#pragma unroll
        for (int j = 0; j < 4; ++j) {
            const int n = n0 + tx * 4 + j;
            float rr = 1.0f / (1.0f + expf(-(accr[i][j] + bih[n] + bhh[n])));
            float zz = 1.0f / (1.0f + expf(-(accz[i][j] + bih[HH + n] + bhh[HH + n])));
            float nn = tanhf(acci[i][j] + bih[2 * HH + n] +
                             rr * (acch[i][j] + bhh[2 * HH + n]));
            float hp = hprev[m * HH + n];
            hnew[m * HH + n] = (1.0f - zz) * nn + zz * hp;
        }
    }
}

// ============================================================
// Orchestration
// ============================================================
extern "C" void kernel_launch(void* const* d_in, const int* in_sizes, int n_in,
                              void* d_out, int out_size)
{
    const float* latent = (const float*)d_in[0];
    const float* target = (const float*)d_in[1];
    const float* Wd1 = (const float*)d_in[2];
    const float* bd1 = (const float*)d_in[3];
    const float* Wd2 = (const float*)d_in[4];
    const float* bd2 = (const float*)d_in[5];
    const float* Wd3 = (const float*)d_in[6];
    const float* bd3 = (const float*)d_in[7];
    const float* Wih = (const float*)d_in[8];
    const float* Whh = (const float*)d_in[9];
    const float* bih = (const float*)d_in[10];
    const float* bhh = (const float*)d_in[11];
    const float* Wm1 = (const float*)d_in[12];
    const float* bm1 = (const float*)d_in[13];
    const float* Wm2 = (const float*)d_in[14];
    const float* bm2 = (const float*)d_in[15];
    const float* Wm3 = (const float*)d_in[16];
    const float* bm3 = (const float*)d_in[17];
    float* out = (float*)d_out;

    float *Hall, *P1, *P2, *t1, *t2, *xbos;
    cudaGetSymbolAddress((void**)&Hall, g_Hall);
    cudaGetSymbolAddress((void**)&P1, g_P1);
    cudaGetSymbolAddress((void**)&P2, g_P2);
    cudaGetSymbolAddress((void**)&t1, g_t1);
    cudaGetSymbolAddress((void**)&t2, g_t2);
    cudaGetSymbolAddress((void**)&xbos, g_xbos);

    // out[:,0,:] = bos ; xbos buffer for step 1
    fill_bos_out<<<(BB * AA) / 256, 256>>>(out);
    fill_xbos<<<(BB * AA) / 256, 256>>>(xbos);

    // h0 = Wd3(tanh(Wd2(tanh(Wd1(latent)))))
    gemm_bias_act<1, false><<<dim3(BB / 64, HH / 64), 256>>>(latent, LAT, Wd1, LAT, bd1, t1, HH);
    gemm_bias_act<1, false><<<dim3(BB / 64, HH / 64), 256>>>(t1, HH, Wd2, HH, bd2, t2, HH);
    gemm_bias_act<0, false><<<dim3(BB / 64, HH / 64), 256>>>(t2, HH, Wd3, HH, bd3, Hall, HH);

    // sequential GRU: step t produces Hall[t] from Hall[t-1]
    for (int t = 1; t < LL; ++t) {
        const float* x;
        long ldx;
        if (t == 1) { x = xbos; ldx = AA; }
        else        { x = target + (size_t)(t - 1) * AA; ldx = (long)LL * AA; }
        gru_step<<<dim3(BB / 64, HH / 64), 256>>>(
            x, ldx,
            Hall + (size_t)(t - 1) * BB * HH,
            Wih, Whh, bih, bhh,
            Hall + (size_t)t * BB * HH);
    }

    // per-step decoder over all 127 steps at once (rows = (t-1)*B + b)
    const long M2 = (long)(LL - 1) * BB;  // 520192
    gemm_bias_act<1, false><<<dim3(M2 / 64, HH / 64), 256>>>(Hall + (size_t)BB * HH, HH, Wm1, HH, bm1, P1, HH);
    gemm_bias_act<1, false><<<dim3(M2 / 64, AA / 64), 256>>>(P1, HH, Wm2, HH, bm2, P2, AA);
    gemm_bias_act<0, true ><<<dim3(M2 / 64, AA / 64), 256>>>(P2, AA, Wm3, AA, bm3, out, 0);
}